// round 1
// baseline (speedup 1.0000x reference)
#include <cuda_runtime.h>
#include <cstdint>

// GatherBlock: out[m, :, :, :] = x[b[m], :, yb[m]*16 : yb[m]*16+16, xb[m]*16 : xb[m]*16+16]
// x: (8, 64, 256, 256) fp32, indices: (1024, 3) int32, out: (1024, 64, 16, 16) fp32.
//
// Pure memory-bound gather-copy. One CTA per m; 256 threads; each thread moves
// 16 float4 (4096 float4 per block = 64KB). All loads/stores 16B-aligned and
// coalesced: tile rows are 16 contiguous floats = 64B segments.

static constexpr int C = 64;
static constexpr int H = 256;
static constexpr int W = 256;
static constexpr int BH = 16;
static constexpr int BW = 16;
static constexpr int CHW = C * H * W;      // 4194304
static constexpr int HW = H * W;           // 65536
static constexpr int VEC_PER_M = C * BH * BW / 4;  // 4096 float4 per output block

__global__ __launch_bounds__(256, 8)
void gather_block_kernel(const float* __restrict__ x,
                         const int* __restrict__ idx,
                         float4* __restrict__ out)
{
    const int m = blockIdx.x;
    const int b  = idx[3 * m + 0];
    const int yb = idx[3 * m + 1];
    const int xb = idx[3 * m + 2];

    // base of the gathered tile: x[b, 0, yb*16, xb*16]
    const float* src = x + (size_t)b * CHW + (size_t)(yb * BH) * W + (size_t)(xb * BW);
    float4* dst = out + (size_t)m * VEC_PER_M;

    const int t = threadIdx.x;

    // v in [0, 4096): c = v>>6, row i = (v>>2)&15, j-vector = v&3
    // Front-batch all 16 loads for MLP, then store.
    float4 r[16];
#pragma unroll
    for (int k = 0; k < 16; k++) {
        const int v = t + k * 256;
        const int c = v >> 6;
        const int i = (v >> 2) & 15;
        const int j = v & 3;
        const float4* s = reinterpret_cast<const float4*>(
            src + (size_t)c * HW + (size_t)i * W) + j;
        r[k] = *s;
    }
#pragma unroll
    for (int k = 0; k < 16; k++) {
        dst[t + k * 256] = r[k];
    }
}

extern "C" void kernel_launch(void* const* d_in, const int* in_sizes, int n_in,
                              void* d_out, int out_size)
{
    const float* x  = (const float*)d_in[0];
    const int* idx  = (const int*)d_in[1];
    float4* out     = (float4*)d_out;

    const int M = in_sizes[1] / 3;  // 1024
    gather_block_kernel<<<M, 256>>>(x, idx, out);
}

// round 2
// speedup vs baseline: 1.0667x; 1.0667x over previous
#include <cuda_runtime.h>
#include <cstdint>

// GatherBlock: out[m, :, :, :] = x[b[m], :, yb[m]*16 : yb[m]*16+16, xb[m]*16 : xb[m]*16+16]
// x: (8, 64, 256, 256) fp32, indices: (1024, 3) int32, out: (1024, 64, 16, 16) fp32.
//
// R2: reduce front-batched LDG count (MLP_p1 16 -> 4) to cut the measured
// multi-CTA L1tex-queue spread (spr_max ~2.0 -> ~1.3 per B300 model), and use
// evict-first streaming stores so the 64MiB output doesn't evict x from L2
// (preserving duplicate-tile read hits).

static constexpr int C = 64;
static constexpr int H = 256;
static constexpr int W = 256;
static constexpr int BH = 16;
static constexpr int BW = 16;
static constexpr int CHW = C * H * W;      // 4194304
static constexpr int HW = H * W;           // 65536
static constexpr int VEC_PER_M = C * BH * BW / 4;  // 4096 float4 per output block

__global__ __launch_bounds__(256, 8)
void gather_block_kernel(const float* __restrict__ x,
                         const int* __restrict__ idx,
                         float4* __restrict__ out)
{
    const int m = blockIdx.x;
    const int b  = idx[3 * m + 0];
    const int yb = idx[3 * m + 1];
    const int xb = idx[3 * m + 2];

    // base of the gathered tile: x[b, 0, yb*16, xb*16]
    const float* src = x + (size_t)b * CHW + (size_t)(yb * BH) * W + (size_t)(xb * BW);
    float4* dst = out + (size_t)m * VEC_PER_M;

    const int t = threadIdx.x;

    // v in [0, 4096): c = v>>6, row i = (v>>2)&15, j-vector = v&3.
    // 4 groups of (4 loads, 4 streaming stores): MLP_p1 = 4.
#pragma unroll
    for (int g = 0; g < 4; g++) {
        float4 r[4];
#pragma unroll
        for (int k = 0; k < 4; k++) {
            const int v = t + (g * 4 + k) * 256;
            const int c = v >> 6;
            const int i = (v >> 2) & 15;
            const int j = v & 3;
            const float4* s = reinterpret_cast<const float4*>(
                src + (size_t)c * HW + (size_t)i * W) + j;
            r[k] = *s;
        }
#pragma unroll
        for (int k = 0; k < 4; k++) {
            __stcs(dst + t + (g * 4 + k) * 256, r[k]);
        }
    }
}

extern "C" void kernel_launch(void* const* d_in, const int* in_sizes, int n_in,
                              void* d_out, int out_size)
{
    const float* x  = (const float*)d_in[0];
    const int* idx  = (const int*)d_in[1];
    float4* out     = (float4*)d_out;

    const int M = in_sizes[1] / 3;  // 1024
    gather_block_kernel<<<M, 256>>>(x, idx, out);
}